// round 13
// baseline (speedup 1.0000x reference)
#include <cuda_runtime.h>

// Problem constants (from reference)
#define NBUS 118
#define NB   4096
#define NN   (NB * NBUS)        // 483328 nodes
#define END  (4 * NN)           // 1933312 no-diag edges
#define EF   (END + NN)         // 2416640 full edges
#define TE   (END + EF)         // 4349952 combined edges

// Scratch (device globals; no cudaMalloc allowed)
__device__ int2  g_sd[TE];       // packed (src,dst) int32: [0,END) no-diag, [END,TE) full
__device__ float g_w[TE];        // edge_attr * 100
__device__ float g_p[NN];        // x[:,0]-x[:,1]
__device__ float g_den[NN];      // ybus diag * 100
__device__ float g_aggr_nd[NN];  // layer aggregation buffer
__device__ float g_aggr_f[NN];   // loss aggregation buffer
__device__ float g_err_dummy[16];
__device__ int   g_is64_nd;
__device__ int   g_is64_f;

// Detect whether an index buffer is genuine int64 or int32 stored under an
// int64 label. Genuine int64 little-endian values < NN have zero high words;
// reading int32 data as int64 fuses adjacent indices into huge values.
__global__ void detect_kernel(const unsigned long long* __restrict__ ei_nd,
                              const unsigned long long* __restrict__ ei_f) {
    if (threadIdx.x == 0 && blockIdx.x == 0) {
        bool nd64 = true, f64 = true;
        #pragma unroll
        for (int i = 0; i < 8; ++i) {
            if (ei_nd[i] >= (unsigned long long)NN) nd64 = false;
            if (ei_f[i]  >= (unsigned long long)NN) f64 = false;
        }
        g_is64_nd = nd64 ? 1 : 0;
        g_is64_f  = f64  ? 1 : 0;
    }
}

__device__ __forceinline__ int load_idx(const void* p, long long i, int is64) {
    return is64 ? (int)((const long long*)p)[i] : ((const int*)p)[i];
}

// One-time conversion: indices -> packed int32 pairs, premul weights,
// node quantities, zero accumulators + errors.
__global__ void prep_kernel(const void* __restrict__ ei_nd,
                            const float* __restrict__ ea_nd,
                            const void* __restrict__ ei_f,
                            const float* __restrict__ ea_f,
                            const float* __restrict__ x,
                            const float* __restrict__ ybus,
                            float* __restrict__ err) {
    int tid = blockIdx.x * blockDim.x + threadIdx.x;
    int stride = gridDim.x * blockDim.x;
    int nd64 = g_is64_nd, f64 = g_is64_f;
    for (int e = tid; e < END; e += stride) {
        g_sd[e] = make_int2(load_idx(ei_nd, e, nd64),
                            load_idx(ei_nd, (long long)END + e, nd64));
        g_w[e]  = ea_nd[e] * 100.0f;
    }
    for (int e = tid; e < EF; e += stride) {
        g_sd[END + e] = make_int2(load_idx(ei_f, e, f64),
                                  load_idx(ei_f, (long long)EF + e, f64));
        g_w[END + e]  = ea_f[e] * 100.0f;
    }
    for (int n = tid; n < NN; n += stride) {
        g_p[n] = x[2 * n] - x[2 * n + 1];
        int b = n / NBUS;
        int r = n - b * NBUS;
        g_den[n] = ybus[(size_t)b * NBUS * NBUS + (size_t)r * NBUS + r] * 100.0f;
        g_aggr_nd[n] = 0.0f;
        g_aggr_f[n]  = 0.0f;
    }
    if (tid < 11) err[tid] = 0.0f;
}

// Fused scatter: edges in [start, start+count). ids < END scatter into
// g_aggr_nd (layer), ids >= END into g_aggr_f (loss). Both read theta[src].
__global__ void scatter_kernel(const float* __restrict__ theta, int start, int count) {
    int t = blockIdx.x * blockDim.x + threadIdx.x;
    if (t >= count) return;
    int e = start + t;
    int2 sd   = g_sd[e];
    float msg = __ldg(&theta[sd.x]) * g_w[e];
    float* aggr = (e < END) ? g_aggr_nd : g_aggr_f;
    atomicAdd(&aggr[sd.y], msg);
}

// Layer 0: theta = 0 -> aggr = 0 -> out = p/den, minus slack-bus value per batch.
__global__ void layer0_kernel(float* __restrict__ out) {
    __shared__ float s_ref;
    int b = blockIdx.x;
    int n = threadIdx.x;          // 128 threads, 118 active
    int i = b * NBUS + n;
    float t = 0.0f;
    if (n < NBUS) t = g_p[i] / g_den[i];
    if (n == 0) s_ref = t;
    __syncthreads();
    if (n < NBUS) out[i] = t - s_ref;
}

// Fused per-iteration epilogue:
//  - if write_out: out = (p - aggr_nd)/den, minus slack per batch; zero aggr_nd
//  - always: err += sum |p - aggr_f| (block reduce + atomic); zero aggr_f
__global__ void layer_err_kernel(float* __restrict__ out, float* __restrict__ err,
                                 int write_out) {
    __shared__ float s_ref;
    __shared__ float s_warp[4];
    int b = blockIdx.x;
    int n = threadIdx.x;          // 128 threads
    int i = b * NBUS + n;
    float t = 0.0f, ae = 0.0f;
    if (n < NBUS) {
        float p = g_p[i];
        if (write_out) {
            float a = g_aggr_nd[i];
            g_aggr_nd[i] = 0.0f;
            t = (p - a) / g_den[i];
        }
        float af = g_aggr_f[i];
        g_aggr_f[i] = 0.0f;
        ae = fabsf(p - af);
    }
    if (n == 0) s_ref = t;
    #pragma unroll
    for (int o = 16; o > 0; o >>= 1)
        ae += __shfl_down_sync(0xffffffffu, ae, o);
    if ((n & 31) == 0) s_warp[n >> 5] = ae;
    __syncthreads();
    if (n == 0)
        atomicAdd(err, s_warp[0] + s_warp[1] + s_warp[2] + s_warp[3]);
    if (write_out && n < NBUS)
        out[i] = t - s_ref;
}

extern "C" void kernel_launch(void* const* d_in, const int* in_sizes, int n_in,
                              void* d_out, int out_size) {
    // Identify inputs by element count (all pairwise distinct), never by position.
    const float* x     = nullptr;   // 2*NN      =   966656
    const void*  ei_nd = nullptr;   // 2*END     =  3866624
    const float* ea_nd = nullptr;   // END       =  1933312
    const void*  ei_f  = nullptr;   // 2*EF      =  4833280
    const float* ea_f  = nullptr;   // EF        =  2416640
    const float* ybus  = nullptr;   // NB*118^2  = 57032704
    for (int i = 0; i < n_in; ++i) {
        switch (in_sizes[i]) {
            case 2 * NN:          x     = (const float*)d_in[i]; break;
            case 2 * END:         ei_nd = d_in[i];               break;
            case END:             ea_nd = (const float*)d_in[i]; break;
            case 2 * EF:          ei_f  = d_in[i];               break;
            case EF:              ea_f  = (const float*)d_in[i]; break;
            case NB * NBUS * NBUS:ybus  = (const float*)d_in[i]; break;
            default: break;       // y (NN elements) unused
        }
    }

    float* out = (float*)d_out;
    float* err;
    if (out_size >= NN + 11) {
        err = out + NN;
    } else {
        void* p = nullptr;
        cudaGetSymbolAddress(&p, g_err_dummy);
        err = (float*)p;
    }

    detect_kernel<<<1, 32>>>((const unsigned long long*)ei_nd,
                             (const unsigned long long*)ei_f);
    prep_kernel<<<9440, 256>>>(ei_nd, ea_nd, ei_f, ea_f, x, ybus, err);
    layer0_kernel<<<NB, 128>>>(out);

    for (int l = 0; l < 10; ++l) {
        scatter_kernel<<<(TE + 255) / 256, 256>>>(out, 0, TE);
        layer_err_kernel<<<NB, 128>>>(out, err + l, 1);
    }
    // Final loss on out_10 (only the full-edge scatter)
    scatter_kernel<<<(EF + 255) / 256, 256>>>(out, END, EF);
    layer_err_kernel<<<NB, 128>>>(out, err + 10, 0);
}

// round 15
// speedup vs baseline: 1.0044x; 1.0044x over previous
#include <cuda_runtime.h>

// Problem constants (from reference)
#define NBUS 118
#define NB   4096
#define NN   (NB * NBUS)        // 483328 nodes
#define END  (4 * NN)           // 1933312 no-diag edges
#define EF   (END + NN)         // 2416640 full edges
#define TE   (END + EF)         // 4349952 combined edges

// Scratch (device globals; no cudaMalloc allowed)
__device__ int2  g_sd[TE];       // packed (src,dst) int32: [0,END) no-diag, [END,TE) full
__device__ float g_w[TE];        // edge_attr * 100
__device__ float g_p[NN];        // x[:,0]-x[:,1]
__device__ float g_den[NN];      // ybus diag * 100
__device__ float g_aggr_nd[NN];  // layer aggregation buffer
__device__ float g_aggr_f[NN];   // loss aggregation buffer
__device__ float g_err_dummy[16];
__device__ int   g_is64_nd;
__device__ int   g_is64_f;

// Detect whether an index buffer is genuine int64 or int32 stored under an
// int64 label. Genuine int64 little-endian values < NN have zero high words;
// reading int32 data as int64 fuses adjacent indices into huge values.
__global__ void detect_kernel(const unsigned long long* __restrict__ ei_nd,
                              const unsigned long long* __restrict__ ei_f) {
    if (threadIdx.x == 0 && blockIdx.x == 0) {
        bool nd64 = true, f64 = true;
        #pragma unroll
        for (int i = 0; i < 8; ++i) {
            if (ei_nd[i] >= (unsigned long long)NN) nd64 = false;
            if (ei_f[i]  >= (unsigned long long)NN) f64 = false;
        }
        g_is64_nd = nd64 ? 1 : 0;
        g_is64_f  = f64  ? 1 : 0;
    }
}

__device__ __forceinline__ int load_idx(const void* p, long long i, int is64) {
    return is64 ? (int)((const long long*)p)[i] : ((const int*)p)[i];
}

// One-time conversion: indices -> packed int32 pairs, premul weights,
// node quantities, zero accumulators + errors.
__global__ void prep_kernel(const void* __restrict__ ei_nd,
                            const float* __restrict__ ea_nd,
                            const void* __restrict__ ei_f,
                            const float* __restrict__ ea_f,
                            const float* __restrict__ x,
                            const float* __restrict__ ybus,
                            float* __restrict__ err) {
    int tid = blockIdx.x * blockDim.x + threadIdx.x;
    int stride = gridDim.x * blockDim.x;
    int nd64 = g_is64_nd, f64 = g_is64_f;
    for (int e = tid; e < END; e += stride) {
        g_sd[e] = make_int2(load_idx(ei_nd, e, nd64),
                            load_idx(ei_nd, (long long)END + e, nd64));
        g_w[e]  = ea_nd[e] * 100.0f;
    }
    for (int e = tid; e < EF; e += stride) {
        g_sd[END + e] = make_int2(load_idx(ei_f, e, f64),
                                  load_idx(ei_f, (long long)EF + e, f64));
        g_w[END + e]  = ea_f[e] * 100.0f;
    }
    for (int n = tid; n < NN; n += stride) {
        g_p[n] = x[2 * n] - x[2 * n + 1];
        int b = n / NBUS;
        int r = n - b * NBUS;
        g_den[n] = ybus[(size_t)b * NBUS * NBUS + (size_t)r * NBUS + r] * 100.0f;
        g_aggr_nd[n] = 0.0f;
        g_aggr_f[n]  = 0.0f;
    }
    if (tid < 11) err[tid] = 0.0f;
}

// Fused scatter: edges in [start, start+count). ids < END scatter into
// g_aggr_nd (layer), ids >= END into g_aggr_f (loss). Both read theta[src].
__global__ void scatter_kernel(const float* __restrict__ theta, int start, int count) {
    int t = blockIdx.x * blockDim.x + threadIdx.x;
    if (t >= count) return;
    int e = start + t;
    int2 sd   = g_sd[e];
    float msg = __ldg(&theta[sd.x]) * g_w[e];
    float* aggr = (e < END) ? g_aggr_nd : g_aggr_f;
    atomicAdd(&aggr[sd.y], msg);
}

// Layer 0: theta = 0 -> aggr = 0 -> out = p/den, minus slack-bus value per batch.
__global__ void layer0_kernel(float* __restrict__ out) {
    __shared__ float s_ref;
    int b = blockIdx.x;
    int n = threadIdx.x;          // 128 threads, 118 active
    int i = b * NBUS + n;
    float t = 0.0f;
    if (n < NBUS) t = g_p[i] / g_den[i];
    if (n == 0) s_ref = t;
    __syncthreads();
    if (n < NBUS) out[i] = t - s_ref;
}

// Fused per-iteration epilogue:
//  - if write_out: out = (p - aggr_nd)/den, minus slack per batch; zero aggr_nd
//  - always: err += sum |p - aggr_f| (block reduce + atomic); zero aggr_f
__global__ void layer_err_kernel(float* __restrict__ out, float* __restrict__ err,
                                 int write_out) {
    __shared__ float s_ref;
    __shared__ float s_warp[4];
    int b = blockIdx.x;
    int n = threadIdx.x;          // 128 threads
    int i = b * NBUS + n;
    float t = 0.0f, ae = 0.0f;
    if (n < NBUS) {
        float p = g_p[i];
        if (write_out) {
            float a = g_aggr_nd[i];
            g_aggr_nd[i] = 0.0f;
            t = (p - a) / g_den[i];
        }
        float af = g_aggr_f[i];
        g_aggr_f[i] = 0.0f;
        ae = fabsf(p - af);
    }
    if (n == 0) s_ref = t;
    #pragma unroll
    for (int o = 16; o > 0; o >>= 1)
        ae += __shfl_down_sync(0xffffffffu, ae, o);
    if ((n & 31) == 0) s_warp[n >> 5] = ae;
    __syncthreads();
    if (n == 0)
        atomicAdd(err, s_warp[0] + s_warp[1] + s_warp[2] + s_warp[3]);
    if (write_out && n < NBUS)
        out[i] = t - s_ref;
}

extern "C" void kernel_launch(void* const* d_in, const int* in_sizes, int n_in,
                              void* d_out, int out_size) {
    // Identify inputs by element count (all pairwise distinct), never by position.
    const float* x     = nullptr;   // 2*NN      =   966656
    const void*  ei_nd = nullptr;   // 2*END     =  3866624
    const float* ea_nd = nullptr;   // END       =  1933312
    const void*  ei_f  = nullptr;   // 2*EF      =  4833280
    const float* ea_f  = nullptr;   // EF        =  2416640
    const float* ybus  = nullptr;   // NB*118^2  = 57032704
    for (int i = 0; i < n_in; ++i) {
        switch (in_sizes[i]) {
            case 2 * NN:          x     = (const float*)d_in[i]; break;
            case 2 * END:         ei_nd = d_in[i];               break;
            case END:             ea_nd = (const float*)d_in[i]; break;
            case 2 * EF:          ei_f  = d_in[i];               break;
            case EF:              ea_f  = (const float*)d_in[i]; break;
            case NB * NBUS * NBUS:ybus  = (const float*)d_in[i]; break;
            default: break;       // y (NN elements) unused
        }
    }

    float* out = (float*)d_out;
    float* err;
    if (out_size >= NN + 11) {
        err = out + NN;
    } else {
        void* p = nullptr;
        cudaGetSymbolAddress(&p, g_err_dummy);
        err = (float*)p;
    }

    detect_kernel<<<1, 32>>>((const unsigned long long*)ei_nd,
                             (const unsigned long long*)ei_f);
    prep_kernel<<<9440, 256>>>(ei_nd, ea_nd, ei_f, ea_f, x, ybus, err);
    layer0_kernel<<<NB, 128>>>(out);

    for (int l = 0; l < 10; ++l) {
        scatter_kernel<<<(TE + 255) / 256, 256>>>(out, 0, TE);
        layer_err_kernel<<<NB, 128>>>(out, err + l, 1);
    }
    // Final loss on out_10 (only the full-edge scatter)
    scatter_kernel<<<(EF + 255) / 256, 256>>>(out, END, EF);
    layer_err_kernel<<<NB, 128>>>(out, err + 10, 0);
}